// round 1
// baseline (speedup 1.0000x reference)
#include <cuda_runtime.h>
#include <cuda_fp16.h>
#include <cstdint>
#include <cstring>

// Problem constants
#define BATCH 32
#define CH    256         // in/out channels
#define HH    56
#define WW    56
#define HPAD  58
#define WPAD  64          // padded width (w_in+1 at col 1..56; cols 0,57..63 zero)
#define HO    28
#define WO    28
#define NPIX  (BATCH*HH*WW)   // 100352

// Conv tiling
#define MTILE 128   // 2 output rows x 64 (56 valid) pixels
#define NTILE 128   // output channels per CTA
#define ASTR  38    // smem A row stride (halves)
#define BSTR  40    // smem B row stride (halves)

// -------- scratch (static device arrays; no allocations allowed) ----------
__device__ __half g_xpad[(size_t)BATCH*CH*HPAD*WPAD];   // 30,408,704 halves (~61MB)
__device__ __half g_wpack[9*256*256];                   // [rs][o][c] sign(W) fp16
__device__ __half g_ybuf[(size_t)BATCH*HH*WW*CH];       // NHWC conv output (~51MB)
__device__ float  g_sum[256];
__device__ float  g_sumsq[256];
__device__ float  g_scale[256];
__device__ float  g_shift[256];

// ---------------------------------------------------------------------------
// Kernel 1: pack weights -> sign fp16, layout [rs=3*r+s][o][c]; also zero stats
// ---------------------------------------------------------------------------
__global__ __launch_bounds__(256) void pack_w_kernel(const float* __restrict__ W)
{
    int idx = blockIdx.x * 256 + threadIdx.x;     // 0 .. 589823
    int c  = idx & 255;
    int o  = (idx >> 8) & 255;
    int rs = idx >> 16;                            // 0..8
    int r  = rs / 3;
    int s  = rs - 3 * r;
    float v = W[(((size_t)o * 256 + c) * 3 + r) * 3 + s];
    float sv = (v > 0.f) ? 1.f : ((v < 0.f) ? -1.f : 0.f);
    g_wpack[idx] = __float2half(sv);
    if (blockIdx.x == 0) {
        g_sum[threadIdx.x]   = 0.f;
        g_sumsq[threadIdx.x] = 0.f;
    }
}

// ---------------------------------------------------------------------------
// Kernel 2: pack x -> fp16 zero-padded [n][c][58][64]
// ---------------------------------------------------------------------------
__global__ __launch_bounds__(256) void pack_x_kernel(const float* __restrict__ x)
{
    size_t idx = (size_t)blockIdx.x * 256 + threadIdx.x;   // < 30,408,704
    int wp = (int)(idx & 63);
    int hp = (int)((idx >> 6) % HPAD);
    size_t rest = idx / (64 * HPAD);
    int c = (int)(rest & 255);
    int n = (int)(rest >> 8);
    float v = 0.f;
    if (wp >= 1 && wp <= WW && hp >= 1 && hp <= HH) {
        v = x[(((size_t)n * CH + c) * HH + (hp - 1)) * WW + (wp - 1)];
    }
    g_xpad[idx] = __float2half(v);
}

// ---------------------------------------------------------------------------
// Kernel 3: binarized conv as 9 shifted GEMMs, f16 MMA fp32 acc.
// grid (2 n-tiles, 28 h-tiles, 32 batch), 256 threads (8 warps, 2m x 4n).
// Writes y (fp16, NHWC) and accumulates per-channel sum/sumsq.
// ---------------------------------------------------------------------------
__global__ __launch_bounds__(256) void conv_kernel()
{
    __shared__ __half AS[2][66][ASTR];         // [rowset][w_in 0..65][c 0..31]
    __shared__ __half BS[3][128][BSTR];        // [s][n][c]
    __shared__ float  sm_s1[128];
    __shared__ float  sm_s2[128];

    const int n0  = blockIdx.x * NTILE;        // channel tile base
    const int h0  = blockIdx.y * 2;            // output row base
    const int nb  = blockIdx.z;                // batch
    const int tid = threadIdx.x;
    const int warp = tid >> 5, lane = tid & 31;
    const int g = lane >> 2, t = lane & 3;
    const int warp_m = warp & 1;               // 0..1  (64 pixels each)
    const int warp_n = warp >> 1;              // 0..3  (32 channels each)

    float acc[4][4][4];
    #pragma unroll
    for (int a = 0; a < 4; a++)
        #pragma unroll
        for (int b = 0; b < 4; b++)
            #pragma unroll
            for (int c = 0; c < 4; c++) acc[a][b][c] = 0.f;

    if (tid < 128) { sm_s1[tid] = 0.f; sm_s2[tid] = 0.f; }
    // zero A halo rows 64..65 once (rows 0..63 are rewritten every iter;
    // rows 58..63 get zeros from the global pad)
    for (int i = tid; i < 2 * 2 * ASTR; i += 256) {
        int rl = i / (2 * ASTR);
        int rr = (i / ASTR) & 1;
        AS[rl][64 + rr][i % ASTR] = __float2half(0.f);
    }

    const __half* xp = g_xpad + (size_t)nb * CH * HPAD * WPAD;

    const int cc = tid >> 3;            // 0..31 channel within block
    const int wq = (tid & 7) * 8;       // 0,8,...,56

    for (int r = 0; r < 3; r++) {
        for (int cb = 0; cb < 8; cb++) {
            __syncthreads();
            // ---- load A: two input rows (h0+r, h0+1+r), 64 cols, 32 ch ----
            {
                const __half* src =
                    xp + (((size_t)(cb * 32 + cc) * HPAD) + (h0 + r)) * WPAD + wq;
                uint4 v0 = *(const uint4*)src;
                uint4 v1 = *(const uint4*)(src + WPAD);
                const __half* h0p = (const __half*)&v0;
                const __half* h1p = (const __half*)&v1;
                #pragma unroll
                for (int j = 0; j < 8; j++) AS[0][wq + j][cc] = h0p[j];
                #pragma unroll
                for (int j = 0; j < 8; j++) AS[1][wq + j][cc] = h1p[j];
            }
            // ---- load B: 3 taps x 128 n x 32 c ----
            #pragma unroll
            for (int it = 0; it < 6; it++) {
                int flat = tid + it * 256;          // 0..1535 (16B chunks)
                int s  = flat >> 9;
                int nn = (flat >> 2) & 127;
                int q  = flat & 3;
                uint4 v = *(const uint4*)(g_wpack +
                           (((size_t)(r * 3 + s) * 256 + (n0 + nn)) * 256) +
                           cb * 32 + q * 8);
                *(uint4*)&BS[s][nn][q * 8] = v;
            }
            __syncthreads();

            // ---- MMA: 3 shifts x 2 k16 steps x 16 mma ----
            #pragma unroll
            for (int s = 0; s < 3; s++) {
                #pragma unroll
                for (int kk = 0; kk < 2; kk++) {
                    uint32_t af[4][4];
                    const int c0 = kk * 16 + 2 * t;
                    #pragma unroll
                    for (int mt = 0; mt < 4; mt++) {
                        int wr = mt * 16 + g + s;
                        af[mt][0] = *(const uint32_t*)&AS[warp_m][wr][c0];
                        af[mt][1] = *(const uint32_t*)&AS[warp_m][wr + 8][c0];
                        af[mt][2] = *(const uint32_t*)&AS[warp_m][wr][c0 + 8];
                        af[mt][3] = *(const uint32_t*)&AS[warp_m][wr + 8][c0 + 8];
                    }
                    uint32_t bf[4][2];
                    #pragma unroll
                    for (int nt = 0; nt < 4; nt++) {
                        int nn = warp_n * 32 + nt * 8 + g;
                        bf[nt][0] = *(const uint32_t*)&BS[s][nn][c0];
                        bf[nt][1] = *(const uint32_t*)&BS[s][nn][c0 + 8];
                    }
                    #pragma unroll
                    for (int mt = 0; mt < 4; mt++) {
                        #pragma unroll
                        for (int nt = 0; nt < 4; nt++) {
                            float* cacc = acc[mt][nt];
                            asm volatile(
                              "mma.sync.aligned.m16n8k16.row.col.f32.f16.f16.f32 "
                              "{%0,%1,%2,%3}, {%4,%5,%6,%7}, {%8,%9}, {%0,%1,%2,%3};\n"
                              : "+f"(cacc[0]), "+f"(cacc[1]), "+f"(cacc[2]), "+f"(cacc[3])
                              : "r"(af[mt][0]), "r"(af[mt][1]), "r"(af[mt][2]), "r"(af[mt][3]),
                                "r"(bf[nt][0]), "r"(bf[nt][1]));
                        }
                    }
                }
            }
        }
    }

    // ---- epilogue: write y (fp16 NHWC) + per-channel partial stats ----
    const int h = h0 + warp_m;
    float s1[4][2], s2[4][2];
    #pragma unroll
    for (int nt = 0; nt < 4; nt++) { s1[nt][0]=s1[nt][1]=s2[nt][0]=s2[nt][1]=0.f; }

    #pragma unroll
    for (int nt = 0; nt < 4; nt++) {
        const int ch0 = n0 + warp_n * 32 + nt * 8 + 2 * t;
        #pragma unroll
        for (int mt = 0; mt < 4; mt++) {
            int w0 = mt * 16 + g;            // always < 56
            float f0 = acc[mt][nt][0], f1 = acc[mt][nt][1];
            __half2 hv = __halves2half2(__float2half(f0), __float2half(f1));
            *(__half2*)(g_ybuf + (((size_t)(nb * HH + h) * WW + w0) * CH) + ch0) = hv;
            s1[nt][0] += f0;  s2[nt][0] += f0 * f0;
            s1[nt][1] += f1;  s2[nt][1] += f1 * f1;
            if (mt < 3) {                    // w0+8 valid only for mt<3
                int w1 = w0 + 8;
                float f2 = acc[mt][nt][2], f3 = acc[mt][nt][3];
                __half2 hv2 = __halves2half2(__float2half(f2), __float2half(f3));
                *(__half2*)(g_ybuf + (((size_t)(nb * HH + h) * WW + w1) * CH) + ch0) = hv2;
                s1[nt][0] += f2;  s2[nt][0] += f2 * f2;
                s1[nt][1] += f3;  s2[nt][1] += f3 * f3;
            }
        }
    }
    // butterfly-reduce over g (lane bits 2..4)
    #pragma unroll
    for (int nt = 0; nt < 4; nt++) {
        #pragma unroll
        for (int p = 0; p < 2; p++) {
            #pragma unroll
            for (int m = 4; m < 32; m <<= 1) {
                s1[nt][p] += __shfl_xor_sync(0xffffffffu, s1[nt][p], m);
                s2[nt][p] += __shfl_xor_sync(0xffffffffu, s2[nt][p], m);
            }
        }
    }
    if (g == 0) {
        #pragma unroll
        for (int nt = 0; nt < 4; nt++) {
            #pragma unroll
            for (int p = 0; p < 2; p++) {
                int chl = warp_n * 32 + nt * 8 + 2 * t + p;
                atomicAdd(&sm_s1[chl], s1[nt][p]);
                atomicAdd(&sm_s2[chl], s2[nt][p]);
            }
        }
    }
    __syncthreads();
    if (tid < 128) {
        atomicAdd(&g_sum[n0 + tid],   sm_s1[tid]);
        atomicAdd(&g_sumsq[n0 + tid], sm_s2[tid]);
    }
}

// ---------------------------------------------------------------------------
// Kernel 4: finalize BN stats -> per-channel scale/shift
// ---------------------------------------------------------------------------
__global__ void stats_kernel(const float* __restrict__ gamma,
                             const float* __restrict__ beta)
{
    int c = threadIdx.x;
    const float inv = 1.f / (float)NPIX;
    float m   = g_sum[c] * inv;
    float var = g_sumsq[c] * inv - m * m;
    float sc  = gamma[c] * rsqrtf(var + 1e-5f);
    g_scale[c] = sc;
    g_shift[c] = beta[c] - m * sc;
}

// ---------------------------------------------------------------------------
// Kernel 5: normalize + ReLU + 2x2 maxpool, NHWC fp16 -> NCHW fp32
// grid (28 ho, 32 n), 256 threads (one per channel)
// ---------------------------------------------------------------------------
__global__ __launch_bounds__(256) void pool_kernel(float* __restrict__ out)
{
    __shared__ float sm[256 * WO];
    const int ho = blockIdx.x;
    const int n  = blockIdx.y;
    const int c  = threadIdx.x;
    const float sc = g_scale[c];
    const float sh = g_shift[c];
    const __half* b0 = g_ybuf + ((size_t)(n * HH + 2 * ho) * WW) * CH + c;
    const __half* b1 = b0 + (size_t)WW * CH;
    #pragma unroll 4
    for (int wo = 0; wo < WO; wo++) {
        float a0 = __half2float(b0[(size_t)(2 * wo)     * CH]);
        float a1 = __half2float(b0[(size_t)(2 * wo + 1) * CH]);
        float a2 = __half2float(b1[(size_t)(2 * wo)     * CH]);
        float a3 = __half2float(b1[(size_t)(2 * wo + 1) * CH]);
        float r0 = fmaxf(a0 * sc + sh, 0.f);
        float r1 = fmaxf(a1 * sc + sh, 0.f);
        float r2 = fmaxf(a2 * sc + sh, 0.f);
        float r3 = fmaxf(a3 * sc + sh, 0.f);
        sm[c * WO + wo] = fmaxf(fmaxf(r0, r1), fmaxf(r2, r3));
    }
    __syncthreads();
    for (int i = threadIdx.x; i < 256 * WO; i += 256) {
        int cc = i / WO, wo = i % WO;
        out[(((size_t)n * CH + cc) * HO + ho) * WO + wo] = sm[i];
    }
}

// ---------------------------------------------------------------------------
extern "C" void kernel_launch(void* const* d_in, const int* in_sizes, int n_in,
                              void* d_out, int out_size)
{
    const float* x     = (const float*)d_in[0];   // [32,256,56,56]
    const float* W     = (const float*)d_in[1];   // [256,256,3,3]
    const float* gamma = (const float*)d_in[2];   // [256]
    const float* beta  = (const float*)d_in[3];   // [256]
    float* out = (float*)d_out;                   // [32,256,28,28]

    pack_w_kernel<<<9 * 256 * 256 / 256, 256>>>(W);
    {
        size_t total = (size_t)BATCH * CH * HPAD * WPAD;
        pack_x_kernel<<<(unsigned)(total / 256), 256>>>(x);
    }
    {
        dim3 grid(2, HH / 2, BATCH);
        conv_kernel<<<grid, 256>>>();
    }
    stats_kernel<<<1, 256>>>(gamma, beta);
    {
        dim3 grid(HO, BATCH);
        pool_kernel<<<grid, 256>>>(out);
    }
}

// round 3
// speedup vs baseline: 1.3220x; 1.3220x over previous
#include <cuda_runtime.h>
#include <cuda_fp16.h>
#include <cstdint>

// ---------------- problem constants ----------------
#define BATCH 32
#define CH    256
#define HH    56
#define WW    56
#define HPAD  58
#define WPAD  64
#define HO    28
#define WO    28
#define NPIX  (BATCH*HH*WW)      // 100352
#define PPB   (HPAD*WPAD)        // padded pixels per image = 3712

// conv tiling
#define NT        128            // output channels per CTA
#define AROWS     130            // 128 pixels + 2 shift halo
#define RSTRB     144            // smem row stride bytes (72 halves) -> conflict-free
#define AOFF      0
#define BOFF      (AROWS*RSTRB)          // 18720
#define STAGE     ((BOFF + 384*RSTRB + 127) & ~127)   // 74112
#define NSTAGE    3
#define DSMEM     (NSTAGE*STAGE)         // 222336

// ---------------- static scratch (zero-initialized) ----------------
__device__ __align__(128) __half g_xpad[(size_t)BATCH*PPB*CH + 4096]; // [n][hp][wp][c]
__device__ __align__(128) __half g_wpack[9*256*256];                  // [rs][o][c]
__device__ __align__(128) __half g_ybuf[(size_t)NPIX*CH];             // NHWC conv out
__device__ float g_sum[256], g_sumsq[256], g_scale[256], g_shift[256];

// ---------------- helpers ----------------
__device__ __forceinline__ uint32_t su32(const void* p) {
    uint32_t a;
    asm("{.reg .u64 t; cvta.to.shared.u64 t, %1; cvt.u32.u64 %0, t;}" : "=r"(a) : "l"(p));
    return a;
}
__device__ __forceinline__ void cp16(uint32_t dst, const void* src) {
    asm volatile("cp.async.cg.shared.global [%0], [%1], 16;" :: "r"(dst), "l"(src));
}

// ---------------------------------------------------------------------------
// Kernel 1: pack weights -> sign fp16 [rs][o][c]; block 0 zeroes stats
// ---------------------------------------------------------------------------
__global__ __launch_bounds__(256) void pack_w_kernel(const float* __restrict__ W)
{
    int idx = blockIdx.x * 256 + threadIdx.x;     // 0 .. 589823
    int c  = idx & 255;
    int o  = (idx >> 8) & 255;
    int rs = idx >> 16;
    int r  = rs / 3;
    int s  = rs - 3 * r;
    float v = W[(((size_t)o * 256 + c) * 3 + r) * 3 + s];
    float sv = (v > 0.f) ? 1.f : ((v < 0.f) ? -1.f : 0.f);
    g_wpack[idx] = __float2half(sv);
    if (blockIdx.x == 0) {
        g_sum[threadIdx.x]   = 0.f;
        g_sumsq[threadIdx.x] = 0.f;
    }
}

// ---------------------------------------------------------------------------
// Kernel 2: transpose-pack x NCHW fp32 -> [n][hp][wp][c] fp16 (interior only;
// pad region stays statically zero). grid (56 h, 32 n), 256 threads.
// ---------------------------------------------------------------------------
__global__ __launch_bounds__(256) void pack_x_kernel(const float* __restrict__ x)
{
    __shared__ __half sm[256][58];
    const int h = blockIdx.x, n = blockIdx.y;
    const int wi = threadIdx.x & 63, cb = threadIdx.x >> 6;   // cb 0..3
    if (wi < 56) {
        const float* src = x + (((size_t)n * 256 + cb) * 56 + h) * 56 + wi;
        #pragma unroll 8
        for (int c8 = 0; c8 < 64; c8++) {
            sm[c8 * 4 + cb][wi] = __float2half(src[(size_t)c8 * 4 * 56 * 56]);
        }
    }
    __syncthreads();
    for (int chunk = threadIdx.x; chunk < 56 * 32; chunk += 256) {
        int w = chunk >> 5, cq = chunk & 31;
        __half tmp[8];
        #pragma unroll
        for (int j = 0; j < 8; j++) tmp[j] = sm[cq * 8 + j][w];
        *(uint4*)(g_xpad + (((size_t)(n * HPAD + h + 1)) * WPAD + (w + 1)) * CH + cq * 8)
            = *(uint4*)tmp;
    }
}

// ---------------------------------------------------------------------------
// Kernel 3: conv via mma.sync, 3-deep cp.async pipeline.
// grid (2 ch-tiles, 28 h-tiles, 32 n), 256 threads (8 warps: 2m x 4n).
// CTA tile: M=128 pixels (2 rows x 64 w), N=128 ch.
// 12 stages = 3 h-taps x 4 blocks of 64 input channels; 3 w-shifts per stage
// are row offsets within the 130-row A tile.
// ---------------------------------------------------------------------------
__global__ __launch_bounds__(256) void conv_kernel()
{
    extern __shared__ __align__(128) char dsm[];

    const int n0  = blockIdx.x * NT;
    const int h0  = blockIdx.y * 2;
    const int nb  = blockIdx.z;
    const int tid = threadIdx.x;
    const int wid = tid >> 5, lane = tid & 31;
    const int g = lane >> 2, t = lane & 3;
    const int warp_m = wid & 1;               // 64 pixels each
    const int warp_n = wid >> 1;              // 32 channels each

    float acc[4][4][4];
    #pragma unroll
    for (int a = 0; a < 4; a++)
        #pragma unroll
        for (int b = 0; b < 4; b++)
            #pragma unroll
            for (int c = 0; c < 4; c++) acc[a][b][c] = 0.f;

    const __half* xp = g_xpad + (size_t)nb * PPB * CH;

    auto load_stage = [&](int st) {
        char* sb = dsm + (st % NSTAGE) * STAGE;
        const int r = st >> 2, kb = st & 3;
        const int pix0 = (h0 + r) * WPAD;
        // A: 130 consecutive padded pixels x 64 ch (16B chunks)
        #pragma unroll 1
        for (int i = tid; i < AROWS * 8; i += 256) {
            int row = i >> 3, q = i & 7;
            cp16(su32(sb + AOFF + row * RSTRB + q * 16),
                 xp + (size_t)(pix0 + row) * CH + kb * 64 + q * 8);
        }
        // B: 3 taps x 128 out-ch x 64 in-ch
        const __half* wp = g_wpack + (size_t)(r * 3) * 65536 + (size_t)n0 * 256 + kb * 64;
        #pragma unroll 1
        for (int i = tid; i < 3072; i += 256) {
            int tap = i >> 10, rem = i & 1023, nn = rem >> 3, q = rem & 7;
            cp16(su32(sb + BOFF + (tap * 128 + nn) * RSTRB + q * 16),
                 wp + (size_t)tap * 65536 + (size_t)nn * 256 + q * 8);
        }
        asm volatile("cp.async.commit_group;" ::: "memory");
    };

    auto compute = [&](int st) {
        const char* sb = dsm + (st % NSTAGE) * STAGE;
        const __half* sA = (const __half*)(sb + AOFF);
        const __half* sB = (const __half*)(sb + BOFF);
        #pragma unroll
        for (int s = 0; s < 3; s++) {
            #pragma unroll
            for (int kk = 0; kk < 4; kk++) {
                const int c0 = kk * 16 + 2 * t;
                uint32_t af[4][4];
                #pragma unroll
                for (int mt = 0; mt < 4; mt++) {
                    int row = warp_m * 64 + mt * 16 + g + s;
                    af[mt][0] = *(const uint32_t*)(sA + row * 72 + c0);
                    af[mt][1] = *(const uint32_t*)(sA + (row + 8) * 72 + c0);
                    af[mt][2] = *(const uint32_t*)(sA + row * 72 + c0 + 8);
                    af[mt][3] = *(const uint32_t*)(sA + (row + 8) * 72 + c0 + 8);
                }
                uint32_t bf[4][2];
                #pragma unroll
                for (int nt = 0; nt < 4; nt++) {
                    int nn = s * 128 + warp_n * 32 + nt * 8 + g;
                    bf[nt][0] = *(const uint32_t*)(sB + nn * 72 + c0);
                    bf[nt][1] = *(const uint32_t*)(sB + nn * 72 + c0 + 8);
                }
                #pragma unroll
                for (int mt = 0; mt < 4; mt++) {
                    #pragma unroll
                    for (int nt = 0; nt < 4; nt++) {
                        float* cacc = acc[mt][nt];
                        asm volatile(
                          "mma.sync.aligned.m16n8k16.row.col.f32.f16.f16.f32 "
                          "{%0,%1,%2,%3}, {%4,%5,%6,%7}, {%8,%9}, {%0,%1,%2,%3};\n"
                          : "+f"(cacc[0]), "+f"(cacc[1]), "+f"(cacc[2]), "+f"(cacc[3])
                          : "r"(af[mt][0]), "r"(af[mt][1]), "r"(af[mt][2]), "r"(af[mt][3]),
                            "r"(bf[nt][0]), "r"(bf[nt][1]));
                    }
                }
            }
        }
    };

    load_stage(0);
    load_stage(1);
    #pragma unroll 1
    for (int st = 0; st < 11; st++) {
        asm volatile("cp.async.wait_group 1;" ::: "memory");
        __syncthreads();                    // stage st visible; all warps past compute(st-1)
        if (st + 2 < 12) load_stage(st + 2);
        compute(st);
    }
    asm volatile("cp.async.wait_group 0;" ::: "memory");
    __syncthreads();
    compute(11);

    // ---- epilogue: acc -> fp16 NHWC ----
    const int h = h0 + warp_m;
    #pragma unroll
    for (int nt = 0; nt < 4; nt++) {
        const int ch0 = n0 + warp_n * 32 + nt * 8 + 2 * t;
        #pragma unroll
        for (int mt = 0; mt < 4; mt++) {
            int w0 = mt * 16 + g;            // < 56 always
            __half2 hv = __floats2half2_rn(acc[mt][nt][0], acc[mt][nt][1]);
            *(__half2*)(g_ybuf + (((size_t)(nb * HH + h) * WW + w0) * CH) + ch0) = hv;
            if (mt < 3) {                    // w0+8 valid only for mt<3
                int w1 = w0 + 8;
                __half2 hv2 = __floats2half2_rn(acc[mt][nt][2], acc[mt][nt][3]);
                *(__half2*)(g_ybuf + (((size_t)(nb * HH + h) * WW + w1) * CH) + ch0) = hv2;
            }
        }
    }
}

// ---------------------------------------------------------------------------
// Kernel 4: per-channel sum/sumsq over NHWC fp16 ybuf (coalesced)
// ---------------------------------------------------------------------------
__global__ __launch_bounds__(256) void stats_reduce()
{
    const int c = threadIdx.x;
    const __half* p = g_ybuf + (size_t)blockIdx.x * 224 * 256 + c;
    float s1 = 0.f, s2 = 0.f;
    #pragma unroll 4
    for (int i = 0; i < 224; i++) {
        float v = __half2float(p[(size_t)i * 256]);
        s1 += v; s2 += v * v;
    }
    atomicAdd(&g_sum[c], s1);
    atomicAdd(&g_sumsq[c], s2);
}

// ---------------------------------------------------------------------------
// Kernel 5: finalize BN stats -> scale/shift
// ---------------------------------------------------------------------------
__global__ void stats_kernel(const float* __restrict__ gamma,
                             const float* __restrict__ beta)
{
    int c = threadIdx.x;
    const float inv = 1.f / (float)NPIX;
    float m   = g_sum[c] * inv;
    float var = g_sumsq[c] * inv - m * m;
    float sc  = gamma[c] * rsqrtf(var + 1e-5f);
    g_scale[c] = sc;
    g_shift[c] = beta[c] - m * sc;
}

// ---------------------------------------------------------------------------
// Kernel 6: normalize + ReLU + 2x2 maxpool, NHWC fp16 -> NCHW fp32
// ---------------------------------------------------------------------------
__global__ __launch_bounds__(256) void pool_kernel(float* __restrict__ out)
{
    __shared__ float sm[256 * WO];
    const int ho = blockIdx.x;
    const int n  = blockIdx.y;
    const int c  = threadIdx.x;
    const float sc = g_scale[c];
    const float sh = g_shift[c];
    const __half* b0 = g_ybuf + ((size_t)(n * HH + 2 * ho) * WW) * CH + c;
    const __half* b1 = b0 + (size_t)WW * CH;
    #pragma unroll 4
    for (int wo = 0; wo < WO; wo++) {
        float a0 = __half2float(b0[(size_t)(2 * wo)     * CH]);
        float a1 = __half2float(b0[(size_t)(2 * wo + 1) * CH]);
        float a2 = __half2float(b1[(size_t)(2 * wo)     * CH]);
        float a3 = __half2float(b1[(size_t)(2 * wo + 1) * CH]);
        float r0 = fmaxf(a0 * sc + sh, 0.f);
        float r1 = fmaxf(a1 * sc + sh, 0.f);
        float r2 = fmaxf(a2 * sc + sh, 0.f);
        float r3 = fmaxf(a3 * sc + sh, 0.f);
        sm[c * WO + wo] = fmaxf(fmaxf(r0, r1), fmaxf(r2, r3));
    }
    __syncthreads();
    for (int i = threadIdx.x; i < 256 * WO; i += 256) {
        int cc = i / WO, wo = i % WO;
        out[(((size_t)n * CH + cc) * HO + ho) * WO + wo] = sm[i];
    }
}

// ---------------------------------------------------------------------------
extern "C" void kernel_launch(void* const* d_in, const int* in_sizes, int n_in,
                              void* d_out, int out_size)
{
    const float* x     = (const float*)d_in[0];
    const float* W     = (const float*)d_in[1];
    const float* gamma = (const float*)d_in[2];
    const float* beta  = (const float*)d_in[3];
    float* out = (float*)d_out;

    pack_w_kernel<<<2304, 256>>>(W);
    pack_x_kernel<<<dim3(HH, BATCH), 256>>>(x);

    cudaFuncSetAttribute(conv_kernel, cudaFuncAttributeMaxDynamicSharedMemorySize, DSMEM);
    conv_kernel<<<dim3(2, HH / 2, BATCH), 256, DSMEM>>>();

    stats_reduce<<<NPIX / 224, 256>>>();
    stats_kernel<<<1, 256>>>(gamma, beta);
    pool_kernel<<<dim3(HO, BATCH), 256>>>(out);
}

// round 4
// speedup vs baseline: 1.4346x; 1.0852x over previous
#include <cuda_runtime.h>
#include <cuda_fp16.h>
#include <cstdint>

// ---------------- problem constants ----------------
#define BATCH 32
#define CH    256
#define HH    56
#define WW    56
#define HPAD  58
#define WPAD  64
#define HO    28
#define WO    28
#define NPIX  (BATCH*HH*WW)      // 100352
#define PPB   (HPAD*WPAD)        // padded pixels per image = 3712

// conv tiling: M=256 pixels (4 h-rows x 64 w), N=128 channels
#define NT        128
#define AROWS     258            // 256 pixels + 2 shift halo
#define RSTRB     144            // smem row stride bytes -> conflict-free LDS
#define AOFF      0
#define BOFF      (AROWS*RSTRB)                        // 37152
#define STAGE     ((BOFF + 384*RSTRB + 127) & ~127)    // 92544
#define NSTAGE    2
#define DSMEM     (NSTAGE*STAGE)                       // 185088

// ---------------- static scratch (zero-initialized) ----------------
__device__ __align__(128) __half g_xpad[(size_t)BATCH*PPB*CH + 4096]; // [n][hp][wp][c]
__device__ __align__(128) __half g_wpack[9*256*256];                  // [rs][o][c]
__device__ __align__(128) __half g_ybuf[(size_t)NPIX*CH];             // NHWC conv out
__device__ float g_sum[256], g_sumsq[256], g_scale[256], g_shift[256];

// ---------------- helpers ----------------
__device__ __forceinline__ uint32_t su32(const void* p) {
    uint32_t a;
    asm("{.reg .u64 t; cvta.to.shared.u64 t, %1; cvt.u32.u64 %0, t;}" : "=r"(a) : "l"(p));
    return a;
}
__device__ __forceinline__ void cp16(uint32_t dst, const void* src) {
    asm volatile("cp.async.cg.shared.global [%0], [%1], 16;" :: "r"(dst), "l"(src));
}

// ---------------------------------------------------------------------------
// Kernel 1: pack weights -> sign fp16 [rs][o][c]; block 0 zeroes stats
// ---------------------------------------------------------------------------
__global__ __launch_bounds__(256) void pack_w_kernel(const float* __restrict__ W)
{
    int idx = blockIdx.x * 256 + threadIdx.x;     // 0 .. 589823
    int c  = idx & 255;
    int o  = (idx >> 8) & 255;
    int rs = idx >> 16;
    int r  = rs / 3;
    int s  = rs - 3 * r;
    float v = W[(((size_t)o * 256 + c) * 3 + r) * 3 + s];
    float sv = (v > 0.f) ? 1.f : ((v < 0.f) ? -1.f : 0.f);
    g_wpack[idx] = __float2half(sv);
    if (blockIdx.x == 0) {
        g_sum[threadIdx.x]   = 0.f;
        g_sumsq[threadIdx.x] = 0.f;
    }
}

// ---------------------------------------------------------------------------
// Kernel 2: transpose-pack x NCHW fp32 -> [n][hp][wp][c] fp16
// ---------------------------------------------------------------------------
__global__ __launch_bounds__(256) void pack_x_kernel(const float* __restrict__ x)
{
    __shared__ __half sm[256][58];
    const int h = blockIdx.x, n = blockIdx.y;
    const int wi = threadIdx.x & 63, cb = threadIdx.x >> 6;   // cb 0..3
    if (wi < 56) {
        const float* src = x + (((size_t)n * 256 + cb) * 56 + h) * 56 + wi;
        #pragma unroll 8
        for (int c8 = 0; c8 < 64; c8++) {
            sm[c8 * 4 + cb][wi] = __float2half(src[(size_t)c8 * 4 * 56 * 56]);
        }
    }
    __syncthreads();
    for (int chunk = threadIdx.x; chunk < 56 * 32; chunk += 256) {
        int w = chunk >> 5, cq = chunk & 31;
        __half tmp[8];
        #pragma unroll
        for (int j = 0; j < 8; j++) tmp[j] = sm[cq * 8 + j][w];
        *(uint4*)(g_xpad + (((size_t)(n * HPAD + h + 1)) * WPAD + (w + 1)) * CH + cq * 8)
            = *(uint4*)tmp;
    }
}

// ---------------------------------------------------------------------------
// Kernel 3: conv via mma.sync, 2-deep cp.async ring, fused BN stats.
// grid (2 ch-tiles, 14 h-tiles, 32 n), 256 threads (8 warps: 4m x 2n).
// CTA tile: M=256 pixels (4 rows x 64 w), N=128 ch.
// 12 stages = 3 h-taps x 4 blocks of 64 input channels; 3 w-shifts per stage.
// ---------------------------------------------------------------------------
__global__ __launch_bounds__(256) void conv_kernel()
{
    extern __shared__ __align__(128) char dsm[];
    __shared__ float sm_s1[128];
    __shared__ float sm_s2[128];

    const int n0  = blockIdx.x * NT;
    const int h0  = blockIdx.y * 4;
    const int nb  = blockIdx.z;
    const int tid = threadIdx.x;
    const int wid = tid >> 5, lane = tid & 31;
    const int g = lane >> 2, t = lane & 3;
    const int warp_m = wid & 3;               // h-row, 64 pixels each
    const int warp_n = wid >> 2;              // 64 channels each

    float acc[4][8][4];
    #pragma unroll
    for (int a = 0; a < 4; a++)
        #pragma unroll
        for (int b = 0; b < 8; b++)
            #pragma unroll
            for (int c = 0; c < 4; c++) acc[a][b][c] = 0.f;

    if (tid < 128) { sm_s1[tid] = 0.f; sm_s2[tid] = 0.f; }

    const __half* xp = g_xpad + (size_t)nb * PPB * CH;

    auto load_stage = [&](int st) {
        char* sb = dsm + (st & 1) * STAGE;
        const int r = st >> 2, kb = st & 3;
        const int pix0 = (h0 + r) * WPAD;
        // A: 258 consecutive padded pixels x 64 ch (16B chunks)
        #pragma unroll 1
        for (int i = tid; i < AROWS * 8; i += 256) {
            int row = i >> 3, q = i & 7;
            cp16(su32(sb + AOFF + row * RSTRB + q * 16),
                 xp + (size_t)(pix0 + row) * CH + kb * 64 + q * 8);
        }
        // B: 3 taps x 128 out-ch x 64 in-ch
        const __half* wp = g_wpack + (size_t)(r * 3) * 65536 + (size_t)n0 * 256 + kb * 64;
        #pragma unroll 1
        for (int i = tid; i < 3072; i += 256) {
            int tap = i >> 10, rem = i & 1023, nn = rem >> 3, q = rem & 7;
            cp16(su32(sb + BOFF + (tap * 128 + nn) * RSTRB + q * 16),
                 wp + (size_t)tap * 65536 + (size_t)nn * 256 + q * 8);
        }
        asm volatile("cp.async.commit_group;" ::: "memory");
    };

    auto compute = [&](int st) {
        const char* sb = dsm + (st & 1) * STAGE;
        const __half* sA = (const __half*)(sb + AOFF);
        const __half* sB = (const __half*)(sb + BOFF);
        #pragma unroll
        for (int s = 0; s < 3; s++) {
            #pragma unroll
            for (int kk = 0; kk < 4; kk++) {
                const int c0 = kk * 16 + 2 * t;
                uint32_t af[4][4];
                #pragma unroll
                for (int mt = 0; mt < 4; mt++) {
                    int row = warp_m * 64 + mt * 16 + g + s;
                    af[mt][0] = *(const uint32_t*)(sA + row * 72 + c0);
                    af[mt][1] = *(const uint32_t*)(sA + (row + 8) * 72 + c0);
                    af[mt][2] = *(const uint32_t*)(sA + row * 72 + c0 + 8);
                    af[mt][3] = *(const uint32_t*)(sA + (row + 8) * 72 + c0 + 8);
                }
                uint32_t bf[8][2];
                #pragma unroll
                for (int nt = 0; nt < 8; nt++) {
                    int nn = s * 128 + warp_n * 64 + nt * 8 + g;
                    bf[nt][0] = *(const uint32_t*)(sB + nn * 72 + c0);
                    bf[nt][1] = *(const uint32_t*)(sB + nn * 72 + c0 + 8);
                }
                #pragma unroll
                for (int mt = 0; mt < 4; mt++) {
                    #pragma unroll
                    for (int nt = 0; nt < 8; nt++) {
                        float* cacc = acc[mt][nt];
                        asm volatile(
                          "mma.sync.aligned.m16n8k16.row.col.f32.f16.f16.f32 "
                          "{%0,%1,%2,%3}, {%4,%5,%6,%7}, {%8,%9}, {%0,%1,%2,%3};\n"
                          : "+f"(cacc[0]), "+f"(cacc[1]), "+f"(cacc[2]), "+f"(cacc[3])
                          : "r"(af[mt][0]), "r"(af[mt][1]), "r"(af[mt][2]), "r"(af[mt][3]),
                            "r"(bf[nt][0]), "r"(bf[nt][1]));
                    }
                }
            }
        }
    };

    load_stage(0);
    load_stage(1);
    #pragma unroll 1
    for (int st = 0; st < 12; st++) {
        if (st < 11)
            asm volatile("cp.async.wait_group 1;" ::: "memory");
        else
            asm volatile("cp.async.wait_group 0;" ::: "memory");
        __syncthreads();                 // stage st visible to all warps
        compute(st);
        if (st + 2 < 12) {
            __syncthreads();             // all warps done reading slot st
            load_stage(st + 2);
        }
    }

    // ---- epilogue: acc -> fp16 NHWC + fused BN stats ----
    const int h = h0 + warp_m;
    float s1[8][2], s2[8][2];
    #pragma unroll
    for (int nt = 0; nt < 8; nt++) { s1[nt][0]=s1[nt][1]=s2[nt][0]=s2[nt][1]=0.f; }

    #pragma unroll
    for (int nt = 0; nt < 8; nt++) {
        const int ch0 = n0 + warp_n * 64 + nt * 8 + 2 * t;
        #pragma unroll
        for (int mt = 0; mt < 4; mt++) {
            int w0 = mt * 16 + g;            // < 56 always
            float f0 = acc[mt][nt][0], f1 = acc[mt][nt][1];
            __half2 hv = __floats2half2_rn(f0, f1);
            *(__half2*)(g_ybuf + (((size_t)(nb * HH + h) * WW + w0) * CH) + ch0) = hv;
            s1[nt][0] += f0;  s2[nt][0] += f0 * f0;
            s1[nt][1] += f1;  s2[nt][1] += f1 * f1;
            if (mt < 3) {                    // w0+8 valid only for mt<3
                int w1 = w0 + 8;
                float f2 = acc[mt][nt][2], f3 = acc[mt][nt][3];
                __half2 hv2 = __floats2half2_rn(f2, f3);
                *(__half2*)(g_ybuf + (((size_t)(nb * HH + h) * WW + w1) * CH) + ch0) = hv2;
                s1[nt][0] += f2;  s2[nt][0] += f2 * f2;
                s1[nt][1] += f3;  s2[nt][1] += f3 * f3;
            }
        }
    }
    // butterfly-reduce over g (lane bits 2..4)
    #pragma unroll
    for (int nt = 0; nt < 8; nt++) {
        #pragma unroll
        for (int p = 0; p < 2; p++) {
            #pragma unroll
            for (int m = 4; m < 32; m <<= 1) {
                s1[nt][p] += __shfl_xor_sync(0xffffffffu, s1[nt][p], m);
                s2[nt][p] += __shfl_xor_sync(0xffffffffu, s2[nt][p], m);
            }
        }
    }
    __syncthreads();     // sm_s1/sm_s2 zeroed before atomics (also after last compute)
    if (g == 0) {
        #pragma unroll
        for (int nt = 0; nt < 8; nt++) {
            #pragma unroll
            for (int p = 0; p < 2; p++) {
                int chl = warp_n * 64 + nt * 8 + 2 * t + p;
                atomicAdd(&sm_s1[chl], s1[nt][p]);
                atomicAdd(&sm_s2[chl], s2[nt][p]);
            }
        }
    }
    __syncthreads();
    if (tid < 128) {
        atomicAdd(&g_sum[n0 + tid],   sm_s1[tid]);
        atomicAdd(&g_sumsq[n0 + tid], sm_s2[tid]);
    }
}

// ---------------------------------------------------------------------------
// Kernel 4: finalize BN stats -> scale/shift
// ---------------------------------------------------------------------------
__global__ void stats_kernel(const float* __restrict__ gamma,
                             const float* __restrict__ beta)
{
    int c = threadIdx.x;
    const float inv = 1.f / (float)NPIX;
    float m   = g_sum[c] * inv;
    float var = g_sumsq[c] * inv - m * m;
    float sc  = gamma[c] * rsqrtf(var + 1e-5f);
    g_scale[c] = sc;
    g_shift[c] = beta[c] - m * sc;
}

// ---------------------------------------------------------------------------
// Kernel 5: normalize + ReLU + 2x2 maxpool, NHWC fp16 -> NCHW fp32
// ---------------------------------------------------------------------------
__global__ __launch_bounds__(256) void pool_kernel(float* __restrict__ out)
{
    __shared__ float sm[256 * WO];
    const int ho = blockIdx.x;
    const int n  = blockIdx.y;
    const int c  = threadIdx.x;
    const float sc = g_scale[c];
    const float sh = g_shift[c];
    const __half* b0 = g_ybuf + ((size_t)(n * HH + 2 * ho) * WW) * CH + c;
    const __half* b1 = b0 + (size_t)WW * CH;
    #pragma unroll 4
    for (int wo = 0; wo < WO; wo++) {
        float a0 = __half2float(b0[(size_t)(2 * wo)     * CH]);
        float a1 = __half2float(b0[(size_t)(2 * wo + 1) * CH]);
        float a2 = __half2float(b1[(size_t)(2 * wo)     * CH]);
        float a3 = __half2float(b1[(size_t)(2 * wo + 1) * CH]);
        float r0 = fmaxf(a0 * sc + sh, 0.f);
        float r1 = fmaxf(a1 * sc + sh, 0.f);
        float r2 = fmaxf(a2 * sc + sh, 0.f);
        float r3 = fmaxf(a3 * sc + sh, 0.f);
        sm[c * WO + wo] = fmaxf(fmaxf(r0, r1), fmaxf(r2, r3));
    }
    __syncthreads();
    for (int i = threadIdx.x; i < 256 * WO; i += 256) {
        int cc = i / WO, wo = i % WO;
        out[(((size_t)n * CH + cc) * HO + ho) * WO + wo] = sm[i];
    }
}

// ---------------------------------------------------------------------------
extern "C" void kernel_launch(void* const* d_in, const int* in_sizes, int n_in,
                              void* d_out, int out_size)
{
    const float* x     = (const float*)d_in[0];
    const float* W     = (const float*)d_in[1];
    const float* gamma = (const float*)d_in[2];
    const float* beta  = (const float*)d_in[3];
    float* out = (float*)d_out;

    pack_w_kernel<<<2304, 256>>>(W);
    pack_x_kernel<<<dim3(HH, BATCH), 256>>>(x);

    cudaFuncSetAttribute(conv_kernel, cudaFuncAttributeMaxDynamicSharedMemorySize, DSMEM);
    conv_kernel<<<dim3(2, HH / 4, BATCH), 256, DSMEM>>>();

    stats_kernel<<<1, 256>>>(gamma, beta);
    pool_kernel<<<dim3(HO, BATCH), 256>>>(out);
}

// round 5
// speedup vs baseline: 1.4768x; 1.0294x over previous
#include <cuda_runtime.h>
#include <cuda_fp16.h>
#include <cstdint>

// ---------------- problem constants ----------------
#define BATCH 32
#define CH    256
#define HH    56
#define WW    56
#define HPAD  58
#define WPAD  64
#define HO    28
#define WO    28
#define NPIX  (BATCH*HH*WW)      // 100352
#define PPB   (HPAD*WPAD)        // padded pixels per image = 3712

// conv tiling: M=256 pixels (4 h-rows x 64 w), N=128 channels
#define NT        128
#define AROWS     258            // 256 pixels + 2 shift halo
#define RSTRB     144            // smem row stride bytes -> conflict-free LDS/LDSM
#define AOFF      0
#define BOFF      (AROWS*RSTRB)                        // 37152
#define STAGE     ((BOFF + 384*RSTRB + 127) & ~127)    // 92544
#define NSTAGE    2
#define DSMEM     (NSTAGE*STAGE)                       // 185088

// ---------------- static scratch (zero-initialized) ----------------
__device__ __align__(128) __half g_xpad[(size_t)BATCH*PPB*CH + 4096]; // [n][hp][wp][c]
__device__ __align__(128) __half g_wpack[9*256*256];                  // [rs][o][c]
__device__ __align__(128) __half g_ybuf[(size_t)NPIX*CH];             // NHWC conv out
__device__ float g_sum[256], g_sumsq[256], g_scale[256], g_shift[256];

// ---------------- helpers ----------------
__device__ __forceinline__ uint32_t su32(const void* p) {
    uint32_t a;
    asm("{.reg .u64 t; cvta.to.shared.u64 t, %1; cvt.u32.u64 %0, t;}" : "=r"(a) : "l"(p));
    return a;
}
__device__ __forceinline__ void cp16(uint32_t dst, const void* src) {
    asm volatile("cp.async.cg.shared.global [%0], [%1], 16;" :: "r"(dst), "l"(src));
}
#define LDSM4(r0, r1, r2, r3, addr)                                        \
    asm volatile("ldmatrix.sync.aligned.m8n8.x4.shared.b16 "               \
                 "{%0,%1,%2,%3}, [%4];"                                    \
                 : "=r"(r0), "=r"(r1), "=r"(r2), "=r"(r3) : "r"(addr))

// ---------------------------------------------------------------------------
// Kernel 1: pack weights -> sign fp16 [rs][o][c]; block 0 zeroes stats
// ---------------------------------------------------------------------------
__global__ __launch_bounds__(256) void pack_w_kernel(const float* __restrict__ W)
{
    int idx = blockIdx.x * 256 + threadIdx.x;     // 0 .. 589823
    int c  = idx & 255;
    int o  = (idx >> 8) & 255;
    int rs = idx >> 16;
    int r  = rs / 3;
    int s  = rs - 3 * r;
    float v = W[(((size_t)o * 256 + c) * 3 + r) * 3 + s];
    float sv = (v > 0.f) ? 1.f : ((v < 0.f) ? -1.f : 0.f);
    g_wpack[idx] = __float2half(sv);
    if (blockIdx.x == 0) {
        g_sum[threadIdx.x]   = 0.f;
        g_sumsq[threadIdx.x] = 0.f;
    }
}

// ---------------------------------------------------------------------------
// Kernel 2: transpose-pack x NCHW fp32 -> [n][hp][wp][c] fp16
// ---------------------------------------------------------------------------
__global__ __launch_bounds__(256) void pack_x_kernel(const float* __restrict__ x)
{
    __shared__ __half sm[256][58];
    const int h = blockIdx.x, n = blockIdx.y;
    const int wi = threadIdx.x & 63, cb = threadIdx.x >> 6;   // cb 0..3
    if (wi < 56) {
        const float* src = x + (((size_t)n * 256 + cb) * 56 + h) * 56 + wi;
        #pragma unroll 8
        for (int c8 = 0; c8 < 64; c8++) {
            sm[c8 * 4 + cb][wi] = __float2half(src[(size_t)c8 * 4 * 56 * 56]);
        }
    }
    __syncthreads();
    for (int chunk = threadIdx.x; chunk < 56 * 32; chunk += 256) {
        int w = chunk >> 5, cq = chunk & 31;
        __half tmp[8];
        #pragma unroll
        for (int j = 0; j < 8; j++) tmp[j] = sm[cq * 8 + j][w];
        *(uint4*)(g_xpad + (((size_t)(n * HPAD + h + 1)) * WPAD + (w + 1)) * CH + cq * 8)
            = *(uint4*)tmp;
    }
}

// dummy: positions conv as launch #4 so ncu's fixed sample window hits it
__global__ void dummy_kernel() {}

// ---------------------------------------------------------------------------
// Kernel 3: conv via mma.sync + ldmatrix, 2-deep cp.async ring, fused stats.
// grid (2 ch-tiles, 14 h-tiles, 32 n), 256 threads (8 warps: 4m x 2n).
// CTA tile: M=256 pixels (4 rows x 64 w), N=128 ch.
// 12 stages = 3 h-taps x 4 blocks of 64 input channels; 3 w-shifts per stage.
// ---------------------------------------------------------------------------
__global__ __launch_bounds__(256) void conv_kernel()
{
    extern __shared__ __align__(128) char dsm[];
    __shared__ float sm_s1[128];
    __shared__ float sm_s2[128];

    const int n0  = blockIdx.x * NT;
    const int h0  = blockIdx.y * 4;
    const int nb  = blockIdx.z;
    const int tid = threadIdx.x;
    const int wid = tid >> 5, lane = tid & 31;
    const int g = lane >> 2, t = lane & 3;
    const int warp_m = wid & 3;               // h-row, 64 pixels each
    const int warp_n = wid >> 2;              // 64 channels each

    // ldmatrix per-lane tile mapping (tile id = lane>>3, row-in-tile = lane&7)
    const int tI = lane >> 3, wI = lane & 7;
    const uint32_t a_ro = (uint32_t)(wI + (tI & 1) * 8);   // A: T1,T3 -> +8 rows
    const uint32_t a_co = (uint32_t)((tI >> 1) * 8);       // A: T2,T3 -> +8 k
    const uint32_t b_ro = (uint32_t)(wI + (tI >> 1) * 8);  // B: T2,T3 -> +8 n
    const uint32_t b_co = (uint32_t)((tI & 1) * 8);        // B: T1,T3 -> +8 k

    float acc[4][8][4];
    #pragma unroll
    for (int a = 0; a < 4; a++)
        #pragma unroll
        for (int b = 0; b < 8; b++)
            #pragma unroll
            for (int c = 0; c < 4; c++) acc[a][b][c] = 0.f;

    if (tid < 128) { sm_s1[tid] = 0.f; sm_s2[tid] = 0.f; }

    const __half* xp = g_xpad + (size_t)nb * PPB * CH;

    auto load_stage = [&](int st) {
        char* sb = dsm + (st & 1) * STAGE;
        const int r = st >> 2, kb = st & 3;
        const int pix0 = (h0 + r) * WPAD;
        #pragma unroll 1
        for (int i = tid; i < AROWS * 8; i += 256) {
            int row = i >> 3, q = i & 7;
            cp16(su32(sb + AOFF + row * RSTRB + q * 16),
                 xp + (size_t)(pix0 + row) * CH + kb * 64 + q * 8);
        }
        const __half* wp = g_wpack + (size_t)(r * 3) * 65536 + (size_t)n0 * 256 + kb * 64;
        #pragma unroll 1
        for (int i = tid; i < 3072; i += 256) {
            int tap = i >> 10, rem = i & 1023, nn = rem >> 3, q = rem & 7;
            cp16(su32(sb + BOFF + (tap * 128 + nn) * RSTRB + q * 16),
                 wp + (size_t)tap * 65536 + (size_t)nn * 256 + q * 8);
        }
        asm volatile("cp.async.commit_group;" ::: "memory");
    };

    auto compute = [&](int st) {
        const char* sb = dsm + (st & 1) * STAGE;
        const uint32_t baseA = su32(sb + AOFF)
                             + (warp_m * 64 + a_ro) * RSTRB + a_co * 2;
        const uint32_t baseB = su32(sb + BOFF)
                             + (warp_n * 64 + b_ro) * RSTRB + b_co * 2;
        #pragma unroll
        for (int s = 0; s < 3; s++) {
            #pragma unroll
            for (int kk = 0; kk < 4; kk++) {
                uint32_t af[4][4];
                #pragma unroll
                for (int mt = 0; mt < 4; mt++) {
                    LDSM4(af[mt][0], af[mt][1], af[mt][2], af[mt][3],
                          baseA + (uint32_t)((mt * 16 + s) * RSTRB + kk * 32));
                }
                uint32_t bf[8][2];
                #pragma unroll
                for (int p = 0; p < 4; p++) {
                    LDSM4(bf[2*p][0], bf[2*p][1], bf[2*p+1][0], bf[2*p+1][1],
                          baseB + (uint32_t)((s * 128 + p * 16) * RSTRB + kk * 32));
                }
                #pragma unroll
                for (int mt = 0; mt < 4; mt++) {
                    #pragma unroll
                    for (int nt = 0; nt < 8; nt++) {
                        float* cacc = acc[mt][nt];
                        asm volatile(
                          "mma.sync.aligned.m16n8k16.row.col.f32.f16.f16.f32 "
                          "{%0,%1,%2,%3}, {%4,%5,%6,%7}, {%8,%9}, {%0,%1,%2,%3};\n"
                          : "+f"(cacc[0]), "+f"(cacc[1]), "+f"(cacc[2]), "+f"(cacc[3])
                          : "r"(af[mt][0]), "r"(af[mt][1]), "r"(af[mt][2]), "r"(af[mt][3]),
                            "r"(bf[nt][0]), "r"(bf[nt][1]));
                    }
                }
            }
        }
    };

    load_stage(0);
    load_stage(1);
    #pragma unroll 1
    for (int st = 0; st < 12; st++) {
        if (st < 11)
            asm volatile("cp.async.wait_group 1;" ::: "memory");
        else
            asm volatile("cp.async.wait_group 0;" ::: "memory");
        __syncthreads();                 // stage st visible to all warps
        compute(st);
        if (st + 2 < 12) {
            __syncthreads();             // all warps done reading slot st
            load_stage(st + 2);
        }
    }

    // ---- epilogue: acc -> fp16 NHWC + fused BN stats ----
    const int h = h0 + warp_m;
    float s1[8][2], s2[8][2];
    #pragma unroll
    for (int nt = 0; nt < 8; nt++) { s1[nt][0]=s1[nt][1]=s2[nt][0]=s2[nt][1]=0.f; }

    #pragma unroll
    for (int nt = 0; nt < 8; nt++) {
        const int ch0 = n0 + warp_n * 64 + nt * 8 + 2 * t;
        #pragma unroll
        for (int mt = 0; mt < 4; mt++) {
            int w0 = mt * 16 + g;            // < 56 always
            float f0 = acc[mt][nt][0], f1 = acc[mt][nt][1];
            __half2 hv = __floats2half2_rn(f0, f1);
            *(__half2*)(g_ybuf + (((size_t)(nb * HH + h) * WW + w0) * CH) + ch0) = hv;
            s1[nt][0] += f0;  s2[nt][0] += f0 * f0;
            s1[nt][1] += f1;  s2[nt][1] += f1 * f1;
            if (mt < 3) {                    // w0+8 valid only for mt<3
                int w1 = w0 + 8;
                float f2 = acc[mt][nt][2], f3 = acc[mt][nt][3];
                __half2 hv2 = __floats2half2_rn(f2, f3);
                *(__half2*)(g_ybuf + (((size_t)(nb * HH + h) * WW + w1) * CH) + ch0) = hv2;
                s1[nt][0] += f2;  s2[nt][0] += f2 * f2;
                s1[nt][1] += f3;  s2[nt][1] += f3 * f3;
            }
        }
    }
    #pragma unroll
    for (int nt = 0; nt < 8; nt++) {
        #pragma unroll
        for (int p = 0; p < 2; p++) {
            #pragma unroll
            for (int m = 4; m < 32; m <<= 1) {
                s1[nt][p] += __shfl_xor_sync(0xffffffffu, s1[nt][p], m);
                s2[nt][p] += __shfl_xor_sync(0xffffffffu, s2[nt][p], m);
            }
        }
    }
    __syncthreads();
    if (g == 0) {
        #pragma unroll
        for (int nt = 0; nt < 8; nt++) {
            #pragma unroll
            for (int p = 0; p < 2; p++) {
                int chl = warp_n * 64 + nt * 8 + 2 * t + p;
                atomicAdd(&sm_s1[chl], s1[nt][p]);
                atomicAdd(&sm_s2[chl], s2[nt][p]);
            }
        }
    }
    __syncthreads();
    if (tid < 128) {
        atomicAdd(&g_sum[n0 + tid],   sm_s1[tid]);
        atomicAdd(&g_sumsq[n0 + tid], sm_s2[tid]);
    }
}

// ---------------------------------------------------------------------------
// Kernel 4: finalize BN stats -> scale/shift
// ---------------------------------------------------------------------------
__global__ void stats_kernel(const float* __restrict__ gamma,
                             const float* __restrict__ beta)
{
    int c = threadIdx.x;
    const float inv = 1.f / (float)NPIX;
    float m   = g_sum[c] * inv;
    float var = g_sumsq[c] * inv - m * m;
    float sc  = gamma[c] * rsqrtf(var + 1e-5f);
    g_scale[c] = sc;
    g_shift[c] = beta[c] - m * sc;
}

// ---------------------------------------------------------------------------
// Kernel 5: normalize + ReLU + 2x2 maxpool, NHWC fp16 -> NCHW fp32
// ---------------------------------------------------------------------------
__global__ __launch_bounds__(256) void pool_kernel(float* __restrict__ out)
{
    __shared__ float sm[256 * WO];
    const int ho = blockIdx.x;
    const int n  = blockIdx.y;
    const int c  = threadIdx.x;
    const float sc = g_scale[c];
    const float sh = g_shift[c];
    const __half* b0 = g_ybuf + ((size_t)(n * HH + 2 * ho) * WW) * CH + c;
    const __half* b1 = b0 + (size_t)WW * CH;
    #pragma unroll 4
    for (int wo = 0; wo < WO; wo++) {
        float a0 = __half2float(b0[(size_t)(2 * wo)     * CH]);
        float a1 = __half2float(b0[(size_t)(2 * wo + 1) * CH]);
        float a2 = __half2float(b1[(size_t)(2 * wo)     * CH]);
        float a3 = __half2float(b1[(size_t)(2 * wo + 1) * CH]);
        float r0 = fmaxf(a0 * sc + sh, 0.f);
        float r1 = fmaxf(a1 * sc + sh, 0.f);
        float r2 = fmaxf(a2 * sc + sh, 0.f);
        float r3 = fmaxf(a3 * sc + sh, 0.f);
        sm[c * WO + wo] = fmaxf(fmaxf(r0, r1), fmaxf(r2, r3));
    }
    __syncthreads();
    for (int i = threadIdx.x; i < 256 * WO; i += 256) {
        int cc = i / WO, wo = i % WO;
        out[(((size_t)n * CH + cc) * HO + ho) * WO + wo] = sm[i];
    }
}

// ---------------------------------------------------------------------------
extern "C" void kernel_launch(void* const* d_in, const int* in_sizes, int n_in,
                              void* d_out, int out_size)
{
    const float* x     = (const float*)d_in[0];
    const float* W     = (const float*)d_in[1];
    const float* gamma = (const float*)d_in[2];
    const float* beta  = (const float*)d_in[3];
    float* out = (float*)d_out;

    pack_w_kernel<<<2304, 256>>>(W);
    pack_x_kernel<<<dim3(HH, BATCH), 256>>>(x);
    dummy_kernel<<<1, 32>>>();          // shift conv into ncu's sample slot (#4)

    cudaFuncSetAttribute(conv_kernel, cudaFuncAttributeMaxDynamicSharedMemorySize, DSMEM);
    conv_kernel<<<dim3(2, HH / 4, BATCH), 256, DSMEM>>>();

    stats_kernel<<<1, 256>>>(gamma, beta);
    pool_kernel<<<dim3(HO, BATCH), 256>>>(out);
}